// round 8
// baseline (speedup 1.0000x reference)
#include <cuda_runtime.h>
#include <cuda_bf16.h>
#include <cstdint>
#include <math.h>

// Problem shapes (fixed for this problem)
#define B   32
#define T   2000
#define R   (B*T)        // 64000 rows, row index r = t*32 + b
#define DX  512          // prenet(256) + cond(256)
#define H   512
#define G   2048         // 4*H gate rows
#define NB_LSTM 128      // persistent CTAs (1/SM, <= SM count) -> 4 hidden units each

// ---------------- scratch (device globals: no allocations allowed) ----------------
__device__ float g_x [(size_t)R * DX];   // prenet output ++ cond   [r][512]
__device__ float g_xg[(size_t)R * G];    // input projections (reused by both layers)
__device__ float g_h0[(size_t)R * H];    // layer0 hidden outputs   [r][512]
__device__ float g_h1[(size_t)R * H];    // layer1 hidden outputs   [r][512]
__device__ float g_hbuf[2 * H * B];      // double-buffered h, layout [unit][b]
__device__ unsigned g_bar_count = 0;
__device__ unsigned g_bar_gen   = 0;

// ---------------- packed f32x2 helpers (sm_103a FFMA2 via PTX) ---------------------
__device__ __forceinline__ unsigned long long pack2(float x, float y) {
    unsigned long long d;
    asm("mov.b64 %0, {%1, %2};" : "=l"(d)
        : "r"(__float_as_uint(x)), "r"(__float_as_uint(y)));
    return d;
}
__device__ __forceinline__ void unpack2(unsigned long long d, float &x, float &y) {
    unsigned lo, hi;
    asm("mov.b64 {%0, %1}, %2;" : "=r"(lo), "=r"(hi) : "l"(d));
    x = __uint_as_float(lo);
    y = __uint_as_float(hi);
}
__device__ __forceinline__ void ffma2(unsigned long long &acc,
                                      unsigned long long a, unsigned long long b) {
    asm("fma.rn.f32x2 %0, %1, %2, %0;" : "+l"(acc) : "l"(a), "l"(b));
}

// ---------------- software grid barrier (capture-safe, works across replays) ------
__device__ __forceinline__ void gbar(unsigned nb, unsigned &gen) {
    __syncthreads();
    if (threadIdx.x == 0) {
        __threadfence();
        unsigned target = gen + 1u;
        if (atomicAdd(&g_bar_count, 1u) == nb - 1u) {
            atomicExch(&g_bar_count, 0u);
            __threadfence();
            atomicExch(&g_bar_gen, target);
        } else {
            while (*((volatile unsigned *)&g_bar_gen) != target) { __nanosleep(32); }
        }
        __threadfence();
        gen = target;
    }
    __syncthreads();
}

// ---------------- prenet: p1 = relu(relu(in*pw0+pb0)@pw1^T+pb1); x = [p1, cond] ---
__global__ void prenet_kernel(const float *__restrict__ inputs,
                              const float *__restrict__ cond,
                              const float *__restrict__ pw0,
                              const float *__restrict__ pb0,
                              const float *__restrict__ pw1,
                              const float *__restrict__ pb1) {
    __shared__ float p0s[8][256];
    __shared__ float sv[8];
    int tid = threadIdx.x;
    int r8  = blockIdx.x * 8;
    if (tid < 8) {
        int r = r8 + tid;
        int t = r >> 5, b = r & 31;
        sv[tid] = inputs[b * T + t];
    }
    __syncthreads();
    float w0v = pw0[tid], b0v = pb0[tid];
#pragma unroll
    for (int p = 0; p < 8; p++)
        p0s[p][tid] = fmaxf(fmaf(sv[p], w0v, b0v), 0.f);
    __syncthreads();

    float acc[8];
#pragma unroll
    for (int p = 0; p < 8; p++) acc[p] = 0.f;
    const float *wrow = pw1 + (size_t)tid * 256;
    for (int j = 0; j < 256; j++) {
        float w = wrow[j];
#pragma unroll
        for (int p = 0; p < 8; p++) acc[p] = fmaf(p0s[p][j], w, acc[p]);
    }
    float b1v = pb1[tid];
#pragma unroll
    for (int p = 0; p < 8; p++) {
        int r = r8 + p;
        g_x[(size_t)r * DX + tid] = fmaxf(acc[p] + b1v, 0.f);
    }
#pragma unroll
    for (int p = 0; p < 8; p++) {
        int r = r8 + p;
        int t = r >> 5, b = r & 31;
        g_x[(size_t)r * DX + 256 + tid] = cond[((size_t)b * T + t) * 256 + tid];
    }
}

// ---------------- GEMM: C[r][n] = b0[n]+b1[n] + sum_k A[r][k]*W[n][k] -------------
// A: [R,512] row-major (g_x or g_h0), W: [2048,512] row-major, C = g_xg [R,2048]
// Inner product accumulated in packed f32x2 pairs (FFMA2) -> FMA pipe halved.
__global__ __launch_bounds__(256, 2) void gemm_kernel(int which,
                                                      const float *__restrict__ Wt,
                                                      const float *__restrict__ b0,
                                                      const float *__restrict__ b1) {
    const float *A = which ? g_h0 : g_x;
    float *C = g_xg;
    const int K = 512, N = G;
    __shared__ float As[8][132];
    __shared__ float Ws[8][132];
    int tid = threadIdx.x;
    int m0 = blockIdx.y * 128, n0 = blockIdx.x * 128;
    int lr = tid >> 1, lq = tid & 1;
    const float *Ap = A  + (size_t)(m0 + lr) * K + lq * 4;
    const float *Wp = Wt + (size_t)(n0 + lr) * K + lq * 4;
    float4 a4 = *(const float4 *)Ap;
    float4 w4 = *(const float4 *)Wp;
    int tx = tid & 15, ty = tid >> 4;
    unsigned long long acc2[8][4];
#pragma unroll
    for (int i = 0; i < 8; i++)
#pragma unroll
        for (int jp = 0; jp < 4; jp++) acc2[i][jp] = 0ull;  // bits of (0.f, 0.f)

    for (int kk = 0; kk < K; kk += 8) {
        As[lq * 4 + 0][lr] = a4.x; As[lq * 4 + 1][lr] = a4.y;
        As[lq * 4 + 2][lr] = a4.z; As[lq * 4 + 3][lr] = a4.w;
        Ws[lq * 4 + 0][lr] = w4.x; Ws[lq * 4 + 1][lr] = w4.y;
        Ws[lq * 4 + 2][lr] = w4.z; Ws[lq * 4 + 3][lr] = w4.w;
        __syncthreads();
        if (kk + 8 < K) {                 // register prefetch of next tile
            a4 = *(const float4 *)(Ap + kk + 8);
            w4 = *(const float4 *)(Wp + kk + 8);
        }
#pragma unroll
        for (int k = 0; k < 8; k++) {
            float af[8];
#pragma unroll
            for (int i = 0; i < 8; i++) af[i] = As[k][ty * 8 + i];
            // same smem addresses as before, consumed as 64-bit j-pairs
            const unsigned long long *wrow =
                (const unsigned long long *)&Ws[k][tx * 8];
            unsigned long long wv[4];
#pragma unroll
            for (int jp = 0; jp < 4; jp++) wv[jp] = wrow[jp];
#pragma unroll
            for (int i = 0; i < 8; i++) {
                unsigned long long a2 = pack2(af[i], af[i]);
#pragma unroll
                for (int jp = 0; jp < 4; jp++) ffma2(acc2[i][jp], a2, wv[jp]);
            }
        }
        __syncthreads();
    }
    float bs[8];
#pragma unroll
    for (int j = 0; j < 8; j++) {
        int n = n0 + tx * 8 + j;
        bs[j] = b0[n] + b1[n];
    }
#pragma unroll
    for (int i = 0; i < 8; i++) {
        size_t off = (size_t)(m0 + ty * 8 + i) * N + n0 + tx * 8;
#pragma unroll
        for (int jp = 0; jp < 4; jp++) {
            float v0, v1;
            unpack2(acc2[i][jp], v0, v1);
            C[off + 2 * jp + 0] = v0 + bs[2 * jp + 0];
            C[off + 2 * jp + 1] = v1 + bs[2 * jp + 1];
        }
    }
}

// ---------------- persistent LSTM layer -------------------------------------------
// 128 CTAs; CTA bid owns hidden units j0..j0+3 (16 gate rows: q*512 + j0 + j).
// whh slice resident in SMEM; h staged per step via L2 (__ldcg); 1 grid barrier/step.
#define LSTM_SMEM ((16 * 512 + 512 * 32 + 16 * 33) * 4)

__global__ void lstm_kernel(const float *__restrict__ whh, int which, int Tn) {
    extern __shared__ float sm[];
    float *ws  = sm;                 // [16][512] weight rows
    float *hs  = sm + 16 * 512;      // [512][32] staged h (k-major)
    float *gsh = hs + 512 * 32;      // [16][33]  gate preacts

    float *hout = which ? g_h1 : g_h0;
    const float *xg = g_xg;

    int tid = threadIdx.x, lane = tid & 31, wid = tid >> 5;
    int bid = blockIdx.x;
    int j0  = bid * 4;

    // load this block's 16 whh rows into SMEM (stays for whole kernel)
    for (int idx = tid * 4; idx < 16 * 512; idx += 256 * 4) {
        int rr = idx >> 9, k = idx & 511;
        int row = ((rr >> 2) * 512) + j0 + (rr & 3);
        *(float4 *)(ws + idx) = *(const float4 *)(whh + (size_t)row * 512 + k);
    }

    unsigned gen = *((volatile unsigned *)&g_bar_gen);

    // zero h buffer 0 (this block's slice)
    if (tid < 128) {
        int j = tid >> 5, b = tid & 31;
        __stcg(&g_hbuf[(j0 + j) * 32 + b], 0.f);
    }
    float c = 0.f;
    gbar(gridDim.x, gen);

    int rr0 = wid, rr1 = wid + 8;
    int row0 = ((rr0 >> 2) * 512) + j0 + (rr0 & 3);
    int row1 = ((rr1 >> 2) * 512) + j0 + (rr1 & 3);
    const float *w0 = ws + rr0 * 512;
    const float *w1 = ws + rr1 * 512;

    for (int t = 0; t < Tn; t++) {
        const float *hb = g_hbuf + (size_t)(t & 1) * (H * B);
        float       *hn = g_hbuf + (size_t)((t + 1) & 1) * (H * B);

        size_t xbase = ((size_t)t * B + lane) * G;
        float acc0 = xg[xbase + row0];
        float acc1 = xg[xbase + row1];

        // stage h [512][32] from L2 (other SMs wrote it; bypass L1)
#pragma unroll
        for (int i = 0; i < 16; i++) {
            int idx = i * 1024 + tid * 4;
            float4 v = __ldcg((const float4 *)(hb + idx));
            *((float4 *)(hs + idx)) = v;
        }
        __syncthreads();

#pragma unroll 8
        for (int k = 0; k < 512; k++) {
            float hv = hs[k * 32 + lane];
            acc0 = fmaf(hv, w0[k], acc0);
            acc1 = fmaf(hv, w1[k], acc1);
        }
        gsh[rr0 * 33 + lane] = acc0;
        gsh[rr1 * 33 + lane] = acc1;
        __syncthreads();

        if (tid < 128) {
            int j = tid >> 5, b = tid & 31;
            float xi = gsh[(0 + j)  * 33 + b];
            float xf = gsh[(4 + j)  * 33 + b];
            float xc = gsh[(8 + j)  * 33 + b];
            float xo = gsh[(12 + j) * 33 + b];
            float ig = 1.f / (1.f + expf(-xi));
            float fg = 1.f / (1.f + expf(-xf));
            float cg = tanhf(xc);
            float og = 1.f / (1.f + expf(-xo));
            c = fg * c + ig * cg;
            float h = og * tanhf(c);
            int unit = j0 + j;
            __stcg(&hn[unit * 32 + b], h);
            hout[((size_t)t * B + b) * H + unit] = h;
        }
        gbar(gridDim.x, gen);
    }
}

// ---------------- FC + mask: out[b][t] = relu(h1[r] . fcw + fcb), masked -----------
__global__ void fc_kernel(const float *__restrict__ fcw,
                          const float *__restrict__ fcb,
                          const unsigned char *__restrict__ masks,
                          float *__restrict__ out) {
    int tid = threadIdx.x, lane = tid & 31, wid = tid >> 5;
    size_t r = (size_t)blockIdx.x * 8 + wid;
    const float *hp = g_h1 + r * H;
    float acc = 0.f;
#pragma unroll
    for (int m = 0; m < 16; m++)
        acc = fmaf(hp[lane + m * 32], fcw[lane + m * 32], acc);
#pragma unroll
    for (int o = 16; o > 0; o >>= 1)
        acc += __shfl_xor_sync(0xffffffffu, acc, o);
    if (lane == 0) {
        int t = (int)(r >> 5), b = (int)(r & 31);
        float v = fmaxf(acc + fcb[0], 0.f);
        if (masks[(size_t)b * T + t]) v = 0.f;
        out[(size_t)b * T + t] = v;
    }
}

// ---------------- launch -----------------------------------------------------------
extern "C" void kernel_launch(void *const *d_in, const int *in_sizes, int n_in,
                              void *d_out, int out_size) {
    const float *inputs = (const float *)d_in[0];
    const float *cond   = (const float *)d_in[1];
    const unsigned char *masks = (const unsigned char *)d_in[2];
    const float *pw0  = (const float *)d_in[3];
    const float *pb0  = (const float *)d_in[4];
    const float *pw1  = (const float *)d_in[5];
    const float *pb1  = (const float *)d_in[6];
    const float *wih0 = (const float *)d_in[7];
    const float *whh0 = (const float *)d_in[8];
    const float *bih0 = (const float *)d_in[9];
    const float *bhh0 = (const float *)d_in[10];
    const float *wih1 = (const float *)d_in[11];
    const float *whh1 = (const float *)d_in[12];
    const float *bih1 = (const float *)d_in[13];
    const float *bhh1 = (const float *)d_in[14];
    const float *fcw  = (const float *)d_in[15];
    const float *fcb  = (const float *)d_in[16];
    float *out = (float *)d_out;

    cudaFuncSetAttribute(lstm_kernel, cudaFuncAttributeMaxDynamicSharedMemorySize,
                         LSTM_SMEM);

    prenet_kernel<<<R / 8, 256>>>(inputs, cond, pw0, pb0, pw1, pb1);
    gemm_kernel<<<dim3(G / 128, R / 128), 256>>>(0, wih0, bih0, bhh0);
    lstm_kernel<<<NB_LSTM, 256, LSTM_SMEM>>>(whh0, 0, T);
    gemm_kernel<<<dim3(G / 128, R / 128), 256>>>(1, wih1, bih1, bhh1);
    lstm_kernel<<<NB_LSTM, 256, LSTM_SMEM>>>(whh1, 1, T);
    fc_kernel<<<R / 8, 256>>>(fcw, fcb, masks, out);
}

// round 9
// speedup vs baseline: 1.2081x; 1.2081x over previous
#include <cuda_runtime.h>
#include <cuda_bf16.h>
#include <cstdint>
#include <math.h>

// Problem shapes (fixed for this problem)
#define B   32
#define T   2000
#define R   (B*T)        // 64000 rows, row index r = t*32 + b
#define DX  512          // prenet(256) + cond(256)
#define H   512
#define G   2048         // 4*H gate rows
#define NB_LSTM 128      // persistent CTAs (1/SM) -> 4 hidden units each

// ---------------- scratch (device globals: no allocations allowed) ----------------
__device__ float g_x [(size_t)R * DX];   // prenet output ++ cond   [r][512]
__device__ float g_xg[(size_t)R * G];    // input projections (reused by both layers)
__device__ float g_h0[(size_t)R * H];    // layer0 hidden outputs   [r][512]
__device__ float g_h1[(size_t)R * H];    // layer1 hidden outputs   [r][512]
__device__ float g_hbuf[2 * B * H];      // double-buffered h, layout [buf][b][unit]
__device__ unsigned g_flags[NB_LSTM];    // per-CTA step-completion flags
__device__ unsigned g_bar_count = 0;
__device__ unsigned g_bar_gen   = 0;

// ---------------- packed f32x2 helpers (sm_103a FFMA2 via PTX) ---------------------
__device__ __forceinline__ unsigned long long pack2(float x, float y) {
    unsigned long long d;
    asm("mov.b64 %0, {%1, %2};" : "=l"(d)
        : "r"(__float_as_uint(x)), "r"(__float_as_uint(y)));
    return d;
}
__device__ __forceinline__ void unpack2(unsigned long long d, float &x, float &y) {
    unsigned lo, hi;
    asm("mov.b64 {%0, %1}, %2;" : "=r"(lo), "=r"(hi) : "l"(d));
    x = __uint_as_float(lo);
    y = __uint_as_float(hi);
}
__device__ __forceinline__ void ffma2(unsigned long long &acc,
                                      unsigned long long a, unsigned long long b) {
    asm("fma.rn.f32x2 %0, %1, %2, %0;" : "+l"(acc) : "l"(a), "l"(b));
}

__device__ __forceinline__ unsigned ldcg_u32v(const unsigned *p) {
    unsigned v;
    asm volatile("ld.global.cg.u32 %0, [%1];" : "=r"(v) : "l"(p));
    return v;
}

// ---------------- software grid barrier (init/epoch only; capture-safe) ------------
__device__ __forceinline__ void gbar(unsigned nb, unsigned &gen) {
    __syncthreads();
    if (threadIdx.x == 0) {
        __threadfence();
        unsigned target = gen + 1u;
        if (atomicAdd(&g_bar_count, 1u) == nb - 1u) {
            atomicExch(&g_bar_count, 0u);
            __threadfence();
            atomicExch(&g_bar_gen, target);
        } else {
            while (*((volatile unsigned *)&g_bar_gen) != target) { __nanosleep(32); }
        }
        __threadfence();
        gen = target;
    }
    __syncthreads();
}

// ---------------- prenet: p1 = relu(relu(in*pw0+pb0)@pw1^T+pb1); x = [p1, cond] ---
__global__ void prenet_kernel(const float *__restrict__ inputs,
                              const float *__restrict__ cond,
                              const float *__restrict__ pw0,
                              const float *__restrict__ pb0,
                              const float *__restrict__ pw1,
                              const float *__restrict__ pb1) {
    __shared__ float p0s[8][256];
    __shared__ float sv[8];
    int tid = threadIdx.x;
    int r8  = blockIdx.x * 8;
    if (tid < 8) {
        int r = r8 + tid;
        int t = r >> 5, b = r & 31;
        sv[tid] = inputs[b * T + t];
    }
    __syncthreads();
    float w0v = pw0[tid], b0v = pb0[tid];
#pragma unroll
    for (int p = 0; p < 8; p++)
        p0s[p][tid] = fmaxf(fmaf(sv[p], w0v, b0v), 0.f);
    __syncthreads();

    float acc[8];
#pragma unroll
    for (int p = 0; p < 8; p++) acc[p] = 0.f;
    const float *wrow = pw1 + (size_t)tid * 256;
    for (int j = 0; j < 256; j++) {
        float w = wrow[j];
#pragma unroll
        for (int p = 0; p < 8; p++) acc[p] = fmaf(p0s[p][j], w, acc[p]);
    }
    float b1v = pb1[tid];
#pragma unroll
    for (int p = 0; p < 8; p++) {
        int r = r8 + p;
        g_x[(size_t)r * DX + tid] = fmaxf(acc[p] + b1v, 0.f);
    }
#pragma unroll
    for (int p = 0; p < 8; p++) {
        int r = r8 + p;
        int t = r >> 5, b = r & 31;
        g_x[(size_t)r * DX + 256 + tid] = cond[((size_t)b * T + t) * 256 + tid];
    }
}

// ---------------- GEMM: C[r][n] = b0[n]+b1[n] + sum_k A[r][k]*W[n][k] -------------
// A: [R,512] row-major (g_x or g_h0), W: [2048,512] row-major, C = g_xg [R,2048]
__global__ __launch_bounds__(256, 2) void gemm_kernel(int which,
                                                      const float *__restrict__ Wt,
                                                      const float *__restrict__ b0,
                                                      const float *__restrict__ b1) {
    const float *A = which ? g_h0 : g_x;
    float *C = g_xg;
    const int K = 512, N = G;
    __shared__ float As[8][132];
    __shared__ float Ws[8][132];
    int tid = threadIdx.x;
    int m0 = blockIdx.y * 128, n0 = blockIdx.x * 128;
    int lr = tid >> 1, lq = tid & 1;
    const float *Ap = A  + (size_t)(m0 + lr) * K + lq * 4;
    const float *Wp = Wt + (size_t)(n0 + lr) * K + lq * 4;
    float4 a4 = *(const float4 *)Ap;
    float4 w4 = *(const float4 *)Wp;
    int tx = tid & 15, ty = tid >> 4;
    unsigned long long acc2[8][4];
#pragma unroll
    for (int i = 0; i < 8; i++)
#pragma unroll
        for (int jp = 0; jp < 4; jp++) acc2[i][jp] = 0ull;

    for (int kk = 0; kk < K; kk += 8) {
        As[lq * 4 + 0][lr] = a4.x; As[lq * 4 + 1][lr] = a4.y;
        As[lq * 4 + 2][lr] = a4.z; As[lq * 4 + 3][lr] = a4.w;
        Ws[lq * 4 + 0][lr] = w4.x; Ws[lq * 4 + 1][lr] = w4.y;
        Ws[lq * 4 + 2][lr] = w4.z; Ws[lq * 4 + 3][lr] = w4.w;
        __syncthreads();
        if (kk + 8 < K) {                 // register prefetch of next tile
            a4 = *(const float4 *)(Ap + kk + 8);
            w4 = *(const float4 *)(Wp + kk + 8);
        }
#pragma unroll
        for (int k = 0; k < 8; k++) {
            float af[8];
#pragma unroll
            for (int i = 0; i < 8; i++) af[i] = As[k][ty * 8 + i];
            const unsigned long long *wrow =
                (const unsigned long long *)&Ws[k][tx * 8];
            unsigned long long wv[4];
#pragma unroll
            for (int jp = 0; jp < 4; jp++) wv[jp] = wrow[jp];
#pragma unroll
            for (int i = 0; i < 8; i++) {
                unsigned long long a2 = pack2(af[i], af[i]);
#pragma unroll
                for (int jp = 0; jp < 4; jp++) ffma2(acc2[i][jp], a2, wv[jp]);
            }
        }
        __syncthreads();
    }
    float bs[8];
#pragma unroll
    for (int j = 0; j < 8; j++) {
        int n = n0 + tx * 8 + j;
        bs[j] = b0[n] + b1[n];
    }
#pragma unroll
    for (int i = 0; i < 8; i++) {
        size_t off = (size_t)(m0 + ty * 8 + i) * N + n0 + tx * 8;
#pragma unroll
        for (int jp = 0; jp < 4; jp++) {
            float v0, v1;
            unpack2(acc2[i][jp], v0, v1);
            C[off + 2 * jp + 0] = v0 + bs[2 * jp + 0];
            C[off + 2 * jp + 1] = v1 + bs[2 * jp + 1];
        }
    }
}

// ---------------- persistent LSTM layer -------------------------------------------
// 128 CTAs; CTA bid owns 4 hidden units (16 gate rows). whh slice in SMEM.
// Sync: per-CTA step flags (producer/consumer), no per-step grid barrier.
// h staged transposed into SMEM as [b][k] (stride 516) for LDS.128 + FFMA2.
#define HS_STRIDE 516
#define LSTM_SMEM ((16 * 512 + 32 * HS_STRIDE + 16 * 33) * 4)

__global__ void lstm_kernel(const float *__restrict__ whh, int which, int Tn) {
    extern __shared__ float sm[];
    float *ws  = sm;                     // [16][512] weight rows
    float *hs  = sm + 16 * 512;          // [32][516] staged h, b-major padded
    float *gsh = hs + 32 * HS_STRIDE;    // [16][33]  gate preacts

    float *hout = which ? g_h1 : g_h0;
    const float *xg = g_xg;

    int tid = threadIdx.x, lane = tid & 31, wid = tid >> 5;
    int bid = blockIdx.x;
    int j0  = bid * 4;

    // load this block's 16 whh rows into SMEM (stays for whole kernel)
    for (int idx = tid * 4; idx < 16 * 512; idx += 256 * 4) {
        int rr = idx >> 9, k = idx & 511;
        int row = ((rr >> 2) * 512) + j0 + (rr & 3);
        *(float4 *)(ws + idx) = *(const float4 *)(whh + (size_t)row * 512 + k);
    }

    unsigned gen = *((volatile unsigned *)&g_bar_gen);

    // zero h_0 (this block's slice, b-major layout) and this CTA's flag
    if (tid < 128) {
        int j = tid >> 5, b = tid & 31;
        __stcg(&g_hbuf[b * H + j0 + j], 0.f);
    }
    if (tid == 0) __stcg(&g_flags[bid], 0u);
    float c = 0.f;
    gbar(gridDim.x, gen);   // epoch: h_0 + zeroed flags visible everywhere

    int rr0 = wid, rr1 = wid + 8;
    int row0 = ((rr0 >> 2) * 512) + j0 + (rr0 & 3);
    int row1 = ((rr1 >> 2) * 512) + j0 + (rr1 & 3);
    const ulonglong2 *w0p = (const ulonglong2 *)(ws + rr0 * 512);
    const ulonglong2 *w1p = (const ulonglong2 *)(ws + rr1 * 512);
    const ulonglong2 *hp  = (const ulonglong2 *)(hs + lane * HS_STRIDE);

    for (int t = 0; t < Tn; t++) {
        const float *hb = g_hbuf + (size_t)(t & 1) * (B * H);
        float       *hn = g_hbuf + (size_t)((t + 1) & 1) * (B * H);

        // xg loads first: DRAM latency overlaps the flag poll
        size_t xbase = ((size_t)t * B + lane) * G;
        float xga = __ldg(xg + xbase + row0);
        float xgb = __ldg(xg + xbase + row1);

        // wait for h_t from all producers (distinct flag per polling thread)
        if (t > 0) {
            if (tid < NB_LSTM) {
                unsigned want = (unsigned)t;
                while (ldcg_u32v(&g_flags[tid]) < want) { __nanosleep(20); }
                __threadfence();
            }
            __syncthreads();
        }

        // stage h_t [b][k] transposed into SMEM (b-major gmem -> contiguous STS.128)
#pragma unroll
        for (int i = 0; i < 16; i++) {
            int idx = i * 1024 + tid * 4;            // [b][k] gmem, contiguous
            float4 v = __ldcg((const float4 *)(hb + idx));
            int b  = idx >> 9;
            int k0 = idx & 511;
            *(float4 *)(hs + b * HS_STRIDE + k0) = v;
        }
        __syncthreads();

        // matvec: 2 gate rows per warp, packed f32x2
        unsigned long long acc0a = 0ull, acc0b = 0ull;
        unsigned long long acc1a = 0ull, acc1b = 0ull;
#pragma unroll 8
        for (int k4 = 0; k4 < 128; k4++) {
            ulonglong2 h2 = hp[k4];
            ulonglong2 wa = w0p[k4];
            ulonglong2 wb = w1p[k4];
            ffma2(acc0a, h2.x, wa.x);
            ffma2(acc0b, h2.y, wa.y);
            ffma2(acc1a, h2.x, wb.x);
            ffma2(acc1b, h2.y, wb.y);
        }
        float s0, s1, s2, s3;
        unpack2(acc0a, s0, s1); unpack2(acc0b, s2, s3);
        float acc0 = xga + ((s0 + s1) + (s2 + s3));
        unpack2(acc1a, s0, s1); unpack2(acc1b, s2, s3);
        float acc1 = xgb + ((s0 + s1) + (s2 + s3));

        gsh[rr0 * 33 + lane] = acc0;
        gsh[rr1 * 33 + lane] = acc1;
        __syncthreads();

        if (tid < 128) {
            int j = tid >> 5, b = tid & 31;
            float xi = gsh[(0 + j)  * 33 + b];
            float xf = gsh[(4 + j)  * 33 + b];
            float xc = gsh[(8 + j)  * 33 + b];
            float xo = gsh[(12 + j) * 33 + b];
            float ig = 1.f / (1.f + expf(-xi));
            float fg = 1.f / (1.f + expf(-xf));
            float cg = tanhf(xc);
            float og = 1.f / (1.f + expf(-xo));
            c = fg * c + ig * cg;
            float h = og * tanhf(c);
            int unit = j0 + j;
            __stcg(&hn[b * H + unit], h);
            hout[((size_t)t * B + b) * H + unit] = h;
        }
        __syncthreads();
        if (tid == 0) {
            __threadfence();                       // h_{t+1} visible before flag
            __stcg(&g_flags[bid], (unsigned)(t + 1));
        }
    }
}

// ---------------- FC + mask: out[b][t] = relu(h1[r] . fcw + fcb), masked -----------
__global__ void fc_kernel(const float *__restrict__ fcw,
                          const float *__restrict__ fcb,
                          const unsigned char *__restrict__ masks,
                          float *__restrict__ out) {
    int tid = threadIdx.x, lane = tid & 31, wid = tid >> 5;
    size_t r = (size_t)blockIdx.x * 8 + wid;
    const float *hp = g_h1 + r * H;
    float acc = 0.f;
#pragma unroll
    for (int m = 0; m < 16; m++)
        acc = fmaf(hp[lane + m * 32], fcw[lane + m * 32], acc);
#pragma unroll
    for (int o = 16; o > 0; o >>= 1)
        acc += __shfl_xor_sync(0xffffffffu, acc, o);
    if (lane == 0) {
        int t = (int)(r >> 5), b = (int)(r & 31);
        float v = fmaxf(acc + fcb[0], 0.f);
        if (masks[(size_t)b * T + t]) v = 0.f;
        out[(size_t)b * T + t] = v;
    }
}

// ---------------- launch -----------------------------------------------------------
extern "C" void kernel_launch(void *const *d_in, const int *in_sizes, int n_in,
                              void *d_out, int out_size) {
    const float *inputs = (const float *)d_in[0];
    const float *cond   = (const float *)d_in[1];
    const unsigned char *masks = (const unsigned char *)d_in[2];
    const float *pw0  = (const float *)d_in[3];
    const float *pb0  = (const float *)d_in[4];
    const float *pw1  = (const float *)d_in[5];
    const float *pb1  = (const float *)d_in[6];
    const float *wih0 = (const float *)d_in[7];
    const float *whh0 = (const float *)d_in[8];
    const float *bih0 = (const float *)d_in[9];
    const float *bhh0 = (const float *)d_in[10];
    const float *wih1 = (const float *)d_in[11];
    const float *whh1 = (const float *)d_in[12];
    const float *bih1 = (const float *)d_in[13];
    const float *bhh1 = (const float *)d_in[14];
    const float *fcw  = (const float *)d_in[15];
    const float *fcb  = (const float *)d_in[16];
    float *out = (float *)d_out;

    cudaFuncSetAttribute(lstm_kernel, cudaFuncAttributeMaxDynamicSharedMemorySize,
                         LSTM_SMEM);

    prenet_kernel<<<R / 8, 256>>>(inputs, cond, pw0, pb0, pw1, pb1);
    gemm_kernel<<<dim3(G / 128, R / 128), 256>>>(0, wih0, bih0, bhh0);
    lstm_kernel<<<NB_LSTM, 256, LSTM_SMEM>>>(whh0, 0, T);
    gemm_kernel<<<dim3(G / 128, R / 128), 256>>>(1, wih1, bih1, bhh1);
    lstm_kernel<<<NB_LSTM, 256, LSTM_SMEM>>>(whh1, 1, T);
    fc_kernel<<<R / 8, 256>>>(fcw, fcb, masks, out);
}